// round 1
// baseline (speedup 1.0000x reference)
#include <cuda_runtime.h>
#include <cstdint>
#include <cmath>

#define B_   64
#define T_   128
#define DIN  2048
#define H_   1024
#define DD   512
#define R_   (B_*T_)      // 8192 rows, row r = t*64 + b (time-major)
#define GSZ  128          // persistent grid size for the recurrence

// ---------------- device scratch (no allocations allowed) ----------------
__device__ float g_bt[(size_t)R_*DIN];        // tf32-rounded bt
__device__ float g_dt[(size_t)R_*DD];         // tf32-rounded masked discount feats
__device__ float g_Wb[(size_t)DIN*3*H_];      // [W_fb | W_sb | W_ib]
__device__ float g_bias[3*H_];                // [e_f | e_s | e_i]
__device__ float g_p[(size_t)R_*3*H_];        // [pf | ps | pi] per (t,b) row
__device__ float g_At[(size_t)R_*DIN];
__device__ float g_Wfsa[(size_t)H_*2*H_];     // [W_fa | W_sa]
__device__ float g_Wia[(size_t)H_*H_];
__device__ float g_Wba[(size_t)H_*DIN];
__device__ float g_E[(size_t)DD*DIN];
__device__ float g_h[2][B_*H_];               // ping-pong hidden state
__device__ float g_f[B_*H_];                  // forget gate for current step
__device__ float g_hs[B_*H_];                 // h * s for current step
__device__ unsigned g_count;                  // grid barrier
__device__ unsigned g_sense;

// ---------------- helpers ----------------
__device__ __forceinline__ float tf32r(float x){
    float y; asm("cvt.rna.tf32.f32 %0, %1;" : "=f"(y) : "f"(x)); return y;
}
__device__ __forceinline__ float sigmf(float x){ return 1.f/(1.f+expf(-x)); }

__device__ __forceinline__ void mma8(float& d0,float& d1,float& d2,float& d3,
    uint32_t a0,uint32_t a1,uint32_t a2,uint32_t a3,uint32_t b0,uint32_t b1){
    asm volatile(
      "mma.sync.aligned.m16n8k8.row.col.f32.tf32.tf32.f32 "
      "{%0,%1,%2,%3},{%4,%5,%6,%7},{%8,%9},{%0,%1,%2,%3};\n"
      : "+f"(d0),"+f"(d1),"+f"(d2),"+f"(d3)
      : "r"(a0),"r"(a1),"r"(a2),"r"(a3),"r"(b0),"r"(b1));
}

// ---------------- prep kernels ----------------
__global__ void prep_bt(const float* __restrict__ x, const float* __restrict__ fi){
    size_t i=(size_t)blockIdx.x*256+threadIdx.x;
    if(i>=(size_t)R_*DIN) return;
    size_t r=i/DIN, d=i%DIN;
    int t=(int)(r>>6), b=(int)(r&63);
    size_t base=(size_t)b*T_+t;
    float bt=x[base*DIN+d]*(1.f-fi[(base*2+1)*DIN+d]);
    g_bt[i]=tf32r(bt);
}
__global__ void prep_dt(const float* __restrict__ fo, const int* __restrict__ midx){
    size_t i=(size_t)blockIdx.x*256+threadIdx.x;
    if(i>=(size_t)R_*DD) return;
    size_t r=i/DD, j=i%DD;
    int t=(int)(r>>6), b=(int)(r&63);
    size_t base=(size_t)b*T_+t;
    g_dt[i]=tf32r(fo[(base*2+1)*DIN+midx[j]]);
}
__global__ void prep_wb(const float* __restrict__ Wfb,const float* __restrict__ Wsb,
                        const float* __restrict__ Wib,const float* __restrict__ ef,
                        const float* __restrict__ es,const float* __restrict__ ei){
    size_t i=(size_t)blockIdx.x*256+threadIdx.x;
    if(i<3*H_) g_bias[i]= (i<H_)? ef[i] : (i<2*H_? es[i-H_] : ei[i-2*H_]);
    if(i>=(size_t)DIN*3*H_) return;
    size_t k=i/(3*H_), n=i%(3*H_);
    float v = (n<H_)? Wfb[k*H_+n] : (n<2*H_? Wsb[k*H_+(n-H_)] : Wib[k*H_+(n-2*H_)]);
    g_Wb[i]=tf32r(v);
}
__global__ void prep_rec(const float* __restrict__ Wfa,const float* __restrict__ Wsa,
                         const float* __restrict__ Wia,const float* __restrict__ Wba,
                         const float* __restrict__ E){
    size_t i=(size_t)blockIdx.x*256+threadIdx.x;
    if(i>=(size_t)H_*DIN) return;     // 2M covers the largest
    size_t k=i/(2*H_), n=i%(2*H_);
    g_Wfsa[i]=tf32r((n<H_)? Wfa[k*H_+n] : Wsa[k*H_+(n-H_)]);
    g_Wba[i]=tf32r(Wba[i]);
    if(i<(size_t)H_*H_)  g_Wia[i]=tf32r(Wia[i]);
    if(i<(size_t)DD*DIN) g_E[i]=tf32r(E[i]);
}

// ---------------- big GEMM: C[M,N] = A[M,K] @ B[K,N] (+bias), tf32 mma ----------------
// mode 0: g_p = g_bt @ g_Wb + g_bias  (K=2048, N=3072)
// mode 1: g_At = g_dt @ g_E           (K=512,  N=2048)
__global__ void __launch_bounds__(256) gemm128(int mode){
    const float *A, *Bm, *bias; float* C; int K, N;
    if(mode==0){ A=g_bt; Bm=g_Wb; C=g_p;  bias=g_bias; K=DIN; N=3*H_; }
    else       { A=g_dt; Bm=g_E;  C=g_At; bias=nullptr; K=DD;  N=DIN; }

    __shared__ float sA[128][36];   // pad 4 -> conflict-free frag loads
    __shared__ float sB[32][136];   // pad 8
    const int tid=threadIdx.x, lane=tid&31, w=tid>>5;
    const int m0=blockIdx.y*128, n0=blockIdx.x*128;
    const int wm=(w>>2)*64, wn=(w&3)*32;      // 2x4 warp grid, 64x32 warp tile
    float acc[4][4][4];
    #pragma unroll
    for(int a=0;a<4;a++) for(int b=0;b<4;b++) for(int c=0;c<4;c++) acc[a][b][c]=0.f;

    for(int k0=0;k0<K;k0+=32){
        #pragma unroll
        for(int j=0;j<4;j++){
            int i=tid+j*256; int r=i>>3, c4=i&7;
            float4 v=*reinterpret_cast<const float4*>(A+(size_t)(m0+r)*K+k0+c4*4);
            sA[r][c4*4+0]=v.x; sA[r][c4*4+1]=v.y; sA[r][c4*4+2]=v.z; sA[r][c4*4+3]=v.w;
        }
        #pragma unroll
        for(int j=0;j<4;j++){
            int i=tid+j*256; int r=i>>5, c4=i&31;
            float4 v=*reinterpret_cast<const float4*>(Bm+(size_t)(k0+r)*N+n0+c4*4);
            sB[r][c4*4+0]=v.x; sB[r][c4*4+1]=v.y; sB[r][c4*4+2]=v.z; sB[r][c4*4+3]=v.w;
        }
        __syncthreads();
        #pragma unroll
        for(int kk=0;kk<4;kk++){
            uint32_t af[4][4];
            #pragma unroll
            for(int mi=0;mi<4;mi++){
                int r=wm+mi*16+(lane>>2), c=kk*8+(lane&3);
                af[mi][0]=__float_as_uint(sA[r  ][c  ]);
                af[mi][1]=__float_as_uint(sA[r+8][c  ]);
                af[mi][2]=__float_as_uint(sA[r  ][c+4]);
                af[mi][3]=__float_as_uint(sA[r+8][c+4]);
            }
            uint32_t bf[4][2];
            #pragma unroll
            for(int nj=0;nj<4;nj++){
                int rr=kk*8+(lane&3), cc=wn+nj*8+(lane>>2);
                bf[nj][0]=__float_as_uint(sB[rr  ][cc]);
                bf[nj][1]=__float_as_uint(sB[rr+4][cc]);
            }
            #pragma unroll
            for(int mi=0;mi<4;mi++)
                #pragma unroll
                for(int nj=0;nj<4;nj++)
                    mma8(acc[mi][nj][0],acc[mi][nj][1],acc[mi][nj][2],acc[mi][nj][3],
                         af[mi][0],af[mi][1],af[mi][2],af[mi][3],bf[nj][0],bf[nj][1]);
        }
        __syncthreads();
    }
    #pragma unroll
    for(int mi=0;mi<4;mi++)
        #pragma unroll
        for(int nj=0;nj<4;nj++){
            int r=m0+wm+mi*16+(lane>>2), c=n0+wn+nj*8+(lane&3)*2;
            float b0=bias?bias[c]:0.f, b1=bias?bias[c+1]:0.f;
            C[(size_t)r*N+c  ]  =acc[mi][nj][0]+b0;
            C[(size_t)r*N+c+1]  =acc[mi][nj][1]+b1;
            C[(size_t)(r+8)*N+c  ]=acc[mi][nj][2]+b0;
            C[(size_t)(r+8)*N+c+1]=acc[mi][nj][3]+b1;
        }
}

// ---------------- init: h=0, hs=0, f(t=0)=sigmoid(pf_0), reset barrier ----------------
__global__ void init_kernel(){
    size_t i=(size_t)blockIdx.x*blockDim.x+threadIdx.x;
    if(i==0){ g_count=0u; g_sense=0u; }
    if(i<(size_t)B_*H_){
        g_h[0][i]=0.f;
        g_hs[i]=0.f;
        size_t b=i/H_, j=i%H_;
        g_f[i]=sigmf(g_p[b*(size_t)(3*H_)+j]);   // row t=0 -> r=b
    }
}

// ---------------- persistent recurrence ----------------
// GEMM: sC[64][NT] = A[64,1024] @ W[:, n0:n0+NT]  (A from gmem via .cg, tf32-round)
template<int NT>
__device__ __forceinline__ void cta_gemm64(const float* __restrict__ Am,
        const float* __restrict__ Wm, int ldw, int n0,
        float (*sA)[36], float (*sW)[40], float (*sC)[33]){
    const int tid=threadIdx.x, lane=tid&31, w=tid>>5;
    const int mi=w&3, njb=w>>2;
    constexpr int NF=NT/8;
    float acc[2][4]={{0.f,0.f,0.f,0.f},{0.f,0.f,0.f,0.f}};
    for(int k0=0;k0<H_;k0+=32){
        #pragma unroll
        for(int j=0;j<2;j++){
            int i=tid+j*256; int r=i>>3, c4=i&7;
            float4 v=__ldcg(reinterpret_cast<const float4*>(Am+(size_t)r*H_+k0+c4*4));
            sA[r][c4*4+0]=tf32r(v.x); sA[r][c4*4+1]=tf32r(v.y);
            sA[r][c4*4+2]=tf32r(v.z); sA[r][c4*4+3]=tf32r(v.w);
        }
        if(NT==32){
            int r=tid>>3, c4=tid&7;
            float4 v=*reinterpret_cast<const float4*>(Wm+(size_t)(k0+r)*ldw+n0+c4*4);
            sW[r][c4*4+0]=v.x; sW[r][c4*4+1]=v.y; sW[r][c4*4+2]=v.z; sW[r][c4*4+3]=v.w;
        } else {
            if(tid<64){
                int r=tid>>1, c4=tid&1;
                float4 v=*reinterpret_cast<const float4*>(Wm+(size_t)(k0+r)*ldw+n0+c4*4);
                sW[r][c4*4+0]=v.x; sW[r][c4*4+1]=v.y; sW[r][c4*4+2]=v.z; sW[r][c4*4+3]=v.w;
            }
        }
        __syncthreads();
        #pragma unroll
        for(int kk=0;kk<4;kk++){
            int r=mi*16+(lane>>2), c=kk*8+(lane&3);
            uint32_t a0=__float_as_uint(sA[r  ][c  ]);
            uint32_t a1=__float_as_uint(sA[r+8][c  ]);
            uint32_t a2=__float_as_uint(sA[r  ][c+4]);
            uint32_t a3=__float_as_uint(sA[r+8][c+4]);
            #pragma unroll
            for(int jf=0;jf<2;jf++){
                int nj=njb*2+jf;
                if(nj<NF){
                    int rr=kk*8+(lane&3), cc=nj*8+(lane>>2);
                    uint32_t b0=__float_as_uint(sW[rr  ][cc]);
                    uint32_t b1=__float_as_uint(sW[rr+4][cc]);
                    mma8(acc[jf][0],acc[jf][1],acc[jf][2],acc[jf][3],a0,a1,a2,a3,b0,b1);
                }
            }
        }
        __syncthreads();
    }
    #pragma unroll
    for(int jf=0;jf<2;jf++){
        int nj=njb*2+jf;
        if(nj<NF){
            int r=mi*16+(lane>>2), c=nj*8+(lane&3)*2;
            sC[r  ][c]=acc[jf][0]; sC[r  ][c+1]=acc[jf][1];
            sC[r+8][c]=acc[jf][2]; sC[r+8][c+1]=acc[jf][3];
        }
    }
    __syncthreads();
}

__device__ __forceinline__ void grid_barrier(unsigned& gen){
    __syncthreads();
    if(threadIdx.x==0){
        __threadfence();
        unsigned a=atomicAdd(&g_count,1u);
        if(a==GSZ-1u){
            g_count=0u;
            __threadfence();
            atomicExch(&g_sense, gen+1u);
        } else {
            while(*((volatile unsigned*)&g_sense) < gen+1u) __nanosleep(32);
            __threadfence();
        }
    }
    __syncthreads();
    gen++;
}

__global__ void __launch_bounds__(256,1) recur_kernel(const float* __restrict__ e_o,
                                                      float* __restrict__ out){
    __shared__ float sA[64][36];
    __shared__ float sW[32][40];
    __shared__ float sC[64][33];
    const int tid=threadIdx.x, cta=blockIdx.x;
    unsigned gen=0;

    for(int t=0;t<T_;t++){
        const float* hOld=g_h[t&1];
        float*       hNew=g_h[(t+1)&1];

        // ---- phase B: c = tanh(pi_t + hs@W_ia); h <- h(1-f)+f*c   (N=1024, 8 cols/CTA)
        {
            int n0=cta*8;
            cta_gemm64<8>(g_hs, g_Wia, H_, n0, sA, sW, sC);
            for(int i=tid;i<B_*8;i+=256){
                int b=i>>3, jj=i&7, n=n0+jj;
                float cpre=sC[b][jj]+g_p[((size_t)t*B_+b)*(3*H_)+2*H_+n];
                float cc=tanhf(cpre);
                float f =__ldcg(&g_f[b*H_+n]);
                float ho=__ldcg(&hOld[b*H_+n]);
                __stcg(&hNew[b*H_+n], ho*(1.f-f)+f*cc);
            }
        }
        grid_barrier(gen);

        // ---- phase C: CTAs 0..63 -> q & output(t);  CTAs 64..127 -> f,s for t+1
        if(cta<64){
            int n0=cta*32;
            cta_gemm64<32>(hNew, g_Wba, DIN, n0, sA, sW, sC);
            for(int i=tid;i<B_*32;i+=256){
                int b=i>>5, jj=i&31, n=n0+jj;
                float q=sC[b][jj];
                float at=g_At[((size_t)t*B_+b)*DIN+n];
                out[((size_t)b*T_+t)*DIN+n]=sigmf(q*(1.f+at)+e_o[n]);
            }
        } else if(t+1<T_){
            int j0=(cta-64)*32;
            cta_gemm64<32>(hNew, g_Wfsa, 2*H_, j0, sA, sW, sC);
            for(int i=tid;i<B_*32;i+=256){
                int b=i>>5, jj=i&31, j=j0+jj;
                float pre=sC[b][jj];
                size_t prow=((size_t)(t+1)*B_+b)*(3*H_);
                if(j<H_){
                    __stcg(&g_f[b*H_+j], sigmf(g_p[prow+j]+pre));
                } else {
                    int js=j-H_;
                    float s=sigmf(g_p[prow+H_+js]+pre);
                    float hv=__ldcg(&hNew[b*H_+js]);
                    __stcg(&g_hs[b*H_+js], hv*s);
                }
            }
        }
        grid_barrier(gen);
    }
}

// ---------------- launch ----------------
extern "C" void kernel_launch(void* const* d_in, const int* /*in_sizes*/, int /*n_in*/,
                              void* d_out, int /*out_size*/){
    const float* x    =(const float*)d_in[0];
    const float* fo   =(const float*)d_in[1];
    const float* fi   =(const float*)d_in[2];
    const float* W_fb =(const float*)d_in[3];
    const float* W_fa =(const float*)d_in[4];
    const float* e_f  =(const float*)d_in[5];
    const float* W_ib =(const float*)d_in[6];
    const float* W_ia =(const float*)d_in[7];
    const float* e_i  =(const float*)d_in[8];
    const float* W_sb =(const float*)d_in[9];
    const float* W_sa =(const float*)d_in[10];
    const float* e_s  =(const float*)d_in[11];
    const float* W_ba =(const float*)d_in[12];
    const float* e_o  =(const float*)d_in[13];
    const float* E    =(const float*)d_in[14];
    const int*   midx =(const int*)d_in[15];
    float* out=(float*)d_out;

    prep_bt<<<(int)(((size_t)R_*DIN+255)/256),256>>>(x,fi);
    prep_dt<<<(int)(((size_t)R_*DD+255)/256),256>>>(fo,midx);
    prep_wb<<<(int)(((size_t)DIN*3*H_+255)/256),256>>>(W_fb,W_sb,W_ib,e_f,e_s,e_i);
    prep_rec<<<(int)(((size_t)H_*DIN+255)/256),256>>>(W_fa,W_sa,W_ia,W_ba,E);

    { dim3 g(3*H_/128, R_/128); gemm128<<<g,256>>>(0); }   // pf|ps|pi
    { dim3 g(DIN/128,  R_/128); gemm128<<<g,256>>>(1); }   // At

    init_kernel<<<256,256>>>();
    recur_kernel<<<GSZ,256>>>(e_o,out);
}

// round 4
// speedup vs baseline: 2.9184x; 2.9184x over previous
#include <cuda_runtime.h>
#include <cuda_fp16.h>
#include <cstdint>
#include <cmath>

#define B_   64
#define T_   128
#define DIN  2048
#define H_   1024
#define DD   512
#define R_   (B_*T_)      // 8192 rows, row r = t*64 + b (time-major)
#define GSZ  128          // persistent grid size

// ---------------- device scratch ----------------
__device__ __half  g_bt16[(size_t)R_*DIN];
__device__ __half  g_dt16[(size_t)R_*DD];
__device__ __half  g_At16[(size_t)R_*DIN];
__device__ float   g_pA[(size_t)T_*128*B_*16];   // [t][cta][b][0..7:pf, 8..15:ps]
__device__ float   g_pB[(size_t)T_*128*B_*8];    // [t][cta][b][pi]
__device__ __half  g_hall[(size_t)(T_+1)*B_*H_]; // h per step (slot 0 = zeros)
__device__ __half  g_hs16[(size_t)B_*H_];        // h*s broadcast buffer
// frag-packed weights: layout [nt][kt16][lane][2]u32
__device__ uint2   g_WbF [(size_t)384*128*32];   // [Wfb|Wsb|Wib] K=2048,N=3072
__device__ uint2   g_WfaF[(size_t)128*64*32];    // K=1024,N=1024
__device__ uint2   g_WsaF[(size_t)128*64*32];
__device__ uint2   g_WiaF[(size_t)128*64*32];
__device__ uint2   g_WbaF[(size_t)256*64*32];    // K=1024,N=2048
__device__ uint2   g_EF  [(size_t)256*32*32];    // K=512, N=2048
__device__ unsigned g_count;
__device__ unsigned g_sense;

// ---------------- helpers ----------------
__device__ __forceinline__ float sigmf(float x){ return 1.f/(1.f+expf(-x)); }
__device__ __forceinline__ uint32_t pk2(float a,float b){
    __half2 h=__floats2half2_rn(a,b); return *reinterpret_cast<uint32_t*>(&h);
}
__device__ __forceinline__ void mma16816(float* c,const uint32_t* a,uint32_t b0,uint32_t b1){
    asm volatile("mma.sync.aligned.m16n8k16.row.col.f32.f16.f16.f32 "
        "{%0,%1,%2,%3},{%4,%5,%6,%7},{%8,%9},{%0,%1,%2,%3};"
        : "+f"(c[0]),"+f"(c[1]),"+f"(c[2]),"+f"(c[3])
        : "r"(a[0]),"r"(a[1]),"r"(a[2]),"r"(a[3]),"r"(b0),"r"(b1));
}
__device__ __forceinline__ void ldm4(uint32_t* a,uint32_t addr){
    asm volatile("ldmatrix.sync.aligned.m8n8.x4.shared.b16 {%0,%1,%2,%3},[%4];"
        : "=r"(a[0]),"=r"(a[1]),"=r"(a[2]),"=r"(a[3]) : "r"(addr));
}
// .ca (L1-allocating) only for addresses never rewritten by other SMs during
// this launch. Cross-CTA recurrent state uses .cg (L2-level).
#define CPA(dst,src)  asm volatile("cp.async.ca.shared.global [%0], [%1], 16;\n"::"r"(dst),"l"(src))
#define CPAG(dst,src) asm volatile("cp.async.cg.shared.global [%0], [%1], 16;\n"::"r"(dst),"l"(src))
#define CPC()  asm volatile("cp.async.commit_group;\n")
#define CPW1() asm volatile("cp.async.wait_group 1;\n")
#define CPW0() asm volatile("cp.async.wait_group 0;\n")

// ---------------- prep: elementwise fp16 conversions ----------------
__global__ void prep_bt(const float* __restrict__ x,const float* __restrict__ fi){
    size_t i=(size_t)blockIdx.x*256+threadIdx.x;
    if(i>=(size_t)R_*DIN) return;
    size_t r=i/DIN, d=i%DIN;
    int t=(int)(r>>6), b=(int)(r&63);
    size_t base=(size_t)b*T_+t;
    g_bt16[i]=__float2half_rn(x[base*DIN+d]*(1.f-fi[(base*2+1)*DIN+d]));
}
__global__ void prep_dt(const float* __restrict__ fo,const int* __restrict__ midx){
    size_t i=(size_t)blockIdx.x*256+threadIdx.x;
    if(i>=(size_t)R_*DD) return;
    size_t r=i/DD, j=i%DD;
    int t=(int)(r>>6), b=(int)(r&63);
    size_t base=(size_t)b*T_+t;
    g_dt16[i]=__float2half_rn(fo[(base*2+1)*DIN+midx[j]]);
}

// ---------------- pack weights into fragment order ----------------
__device__ __forceinline__ void pack_one(const float* __restrict__ W,int N,int KT16,
                                         size_t i,uint2* __restrict__ dst){
    int lane=(int)(i&31); size_t q=i>>5;
    int kt=(int)(q%KT16); size_t nt=q/KT16;
    int n=(int)nt*8+(lane>>2), k=kt*16+(lane&3)*2;
    uint2 v;
    v.x=pk2(W[(size_t)k*N+n],     W[(size_t)(k+1)*N+n]);
    v.y=pk2(W[(size_t)(k+8)*N+n], W[(size_t)(k+9)*N+n]);
    dst[i]=v;
}
__global__ void pack_all(const float* __restrict__ Wfb,const float* __restrict__ Wsb,
                         const float* __restrict__ Wib,const float* __restrict__ Wfa,
                         const float* __restrict__ Wsa,const float* __restrict__ Wia,
                         const float* __restrict__ Wba,const float* __restrict__ E){
    size_t g=(size_t)blockIdx.x*256+threadIdx.x;
    const size_t n_wb=(size_t)384*128*32;
    const size_t n_sq=(size_t)128*64*32;
    const size_t n_ba=(size_t)256*64*32;
    const size_t n_e =(size_t)256*32*32;
    if(g<n_wb){
        int lane=(int)(g&31); size_t q=g>>5;
        int kt=(int)(q%128); size_t nt=q/128;
        int n=(int)nt*8+(lane>>2), k=kt*16+(lane&3)*2;
        const float* W; int nn;
        if(n<1024){W=Wfb;nn=n;} else if(n<2048){W=Wsb;nn=n-1024;} else {W=Wib;nn=n-2048;}
        uint2 v;
        v.x=pk2(W[(size_t)k*H_+nn],     W[(size_t)(k+1)*H_+nn]);
        v.y=pk2(W[(size_t)(k+8)*H_+nn], W[(size_t)(k+9)*H_+nn]);
        g_WbF[g]=v; return;
    }
    g-=n_wb;
    if(g<n_sq){ pack_one(Wfa,H_,64,g,g_WfaF); return; }
    g-=n_sq;
    if(g<n_sq){ pack_one(Wsa,H_,64,g,g_WsaF); return; }
    g-=n_sq;
    if(g<n_sq){ pack_one(Wia,H_,64,g,g_WiaF); return; }
    g-=n_sq;
    if(g<n_ba){ pack_one(Wba,DIN,64,g,g_WbaF); return; }
    g-=n_ba;
    if(g<n_e ){ pack_one(E,DIN,32,g,g_EF); return; }
}

// ---------------- init ----------------
__global__ void init_kernel(){
    size_t i=(size_t)blockIdx.x*256+threadIdx.x;
    if(i==0){ g_count=0u; g_sense=0u; }
    if(i<8192) reinterpret_cast<uint4*>(g_hall)[i]=make_uint4(0,0,0,0); // slot 0 = zeros
}

// ---------------- big fp16 GEMM, 128x128 CTA tile ----------------
// A and BF are resolved IN-KERNEL (device symbols are not valid host-side!).
// MODE 0: p = bt@Wb + bias -> scattered to g_pA/g_pB   (K=2048,N=3072)
// MODE 1: At16 = dt@E                                   (K=512, N=2048)
// MODE 2: out = sigmoid(q*(1+At)+e_o), q = hall@Wba     (K=1024,N=2048)
template<int MODE>
__global__ void __launch_bounds__(256) gemm_fp16(
    const float* __restrict__ e0,const float* __restrict__ e1,
    const float* __restrict__ e2,float* __restrict__ outp)
{
    constexpr int K   =(MODE==0)?2048:((MODE==1)?512:1024);
    constexpr int KT16=K/16;
    constexpr int NKT =K/32;
    const __half* A =(MODE==0)? g_bt16 : ((MODE==1)? g_dt16 : g_hall+(size_t)B_*H_);
    const uint2*  BF=(MODE==0)? g_WbF  : ((MODE==1)? g_EF   : g_WbaF);

    __shared__ __align__(16) unsigned char sA[2][128*80];
    __shared__ __align__(16) unsigned char sB[2][8192];
    const int tid=threadIdx.x, lane=tid&31, w=tid>>5;
    const int m0=blockIdx.y*128, n0=blockIdx.x*128;
    const int wm=(w>>2)*64, wn=(w&3)*32;
    const uint32_t sAu=(uint32_t)__cvta_generic_to_shared(&sA[0][0]);
    float acc[4][4][4]={};

    auto stage=[&](int kt,int bf){
        #pragma unroll
        for(int i=0;i<2;i++){
            int idx=tid+i*256; int r=idx>>2,c=idx&3;
            uint32_t dst=sAu+bf*(128*80)+r*80+c*16;
            const char* src=(const char*)A+((size_t)(m0+r)*K+kt*32)*2+c*16;
            CPA(dst,src);
        }
        #pragma unroll
        for(int i=0;i<2;i++){
            int idx=tid+i*256; int nt=idx>>5,ch=idx&31;
            uint32_t dst=(uint32_t)__cvta_generic_to_shared(&sB[bf][0])+nt*512+ch*16;
            const char* src=(const char*)BF+(((size_t)(n0/8+nt)*KT16+(size_t)kt*2)*256)+ch*16;
            CPA(dst,src);
        }
        CPC();
    };
    stage(0,0);
    for(int kt=0;kt<NKT;kt++){
        int cur=kt&1;
        if(kt+1<NKT){ stage(kt+1,cur^1); CPW1(); } else { CPW0(); }
        __syncthreads();
        #pragma unroll
        for(int kk=0;kk<2;kk++){
            uint32_t a[4][4];
            #pragma unroll
            for(int mi=0;mi<4;mi++){
                int row=wm+mi*16+(lane&7)+((lane>>3)&1)*8;
                ldm4(a[mi], sAu+cur*(128*80)+row*80+kk*32+(lane>>4)*16);
            }
            #pragma unroll
            for(int nj=0;nj<4;nj++){
                const uint2 b=*reinterpret_cast<const uint2*>(&sB[cur][((wn>>3)+nj)*512+kk*256+lane*8]);
                #pragma unroll
                for(int mi=0;mi<4;mi++) mma16816(acc[mi][nj],a[mi],b.x,b.y);
            }
        }
        __syncthreads();
    }
    // epilogue
    #pragma unroll
    for(int mi=0;mi<4;mi++)
    #pragma unroll
    for(int nj=0;nj<4;nj++){
        int c=n0+wn+nj*8+(lane&3)*2;
        #pragma unroll
        for(int p=0;p<2;p++){
            int r=m0+wm+mi*16+(lane>>2)+p*8;
            float d0=acc[mi][nj][p*2], d1=acc[mi][nj][p*2+1];
            int t=r>>6,b=r&63;
            if(MODE==0){
                if(c<1024){
                    float* dst=&g_pA[(((size_t)t*128+(c>>3))*64+b)*16+(c&7)];
                    dst[0]=d0+e0[c]; dst[1]=d1+e0[c+1];
                } else if(c<2048){
                    int n=c-1024;
                    float* dst=&g_pA[(((size_t)t*128+(n>>3))*64+b)*16+8+(n&7)];
                    dst[0]=d0+e1[n]; dst[1]=d1+e1[n+1];
                } else {
                    int n=c-2048;
                    float* dst=&g_pB[(((size_t)t*128+(n>>3))*64+b)*8+(n&7)];
                    dst[0]=d0+e2[n]; dst[1]=d1+e2[n+1];
                }
            } else if(MODE==1){
                *reinterpret_cast<__half2*>(&g_At16[(size_t)r*DIN+c])=__floats2half2_rn(d0,d1);
            } else {
                __half2 ah=*reinterpret_cast<const __half2*>(&g_At16[(size_t)r*DIN+c]);
                float a0=__half2float(__low2half(ah)), a1=__half2float(__high2half(ah));
                float o0=sigmf(d0*(1.f+a0)+e0[c]);
                float o1=sigmf(d1*(1.f+a1)+e0[c+1]);
                *reinterpret_cast<float2*>(&outp[((size_t)b*T_+t)*DIN+c])=make_float2(o0,o1);
            }
        }
    }
}

// ---------------- persistent recurrence ----------------
// dyn smem layout (bytes):
#define WFA_OFF 0          // 16384  [64 kt16][32 lane][u64]
#define WSA_OFF 16384      // 16384
#define WIA_OFF 32768      // 16384
#define A_OFF   49152      // 2 x 64*272 = 34816 (kTile=128 halves, row stride 272B)
#define SC_OFF  83968      // 2 x 64 x 16 f32 = 8192 (split-K partials)
#define SH_OFF  92160      // 64x8 f32
#define SF_OFF  94208      // 64x8 f32
#define DYN_SZ  96256

__device__ __forceinline__ void grid_barrier(unsigned& gen){
    __syncthreads();
    if(threadIdx.x==0){
        __threadfence();
        unsigned a=atomicAdd(&g_count,1u);
        if(a==GSZ-1u){
            g_count=0u;
            __threadfence();
            atomicExch(&g_sense, gen+1u);
        } else {
            while(*((volatile unsigned*)&g_sense) < gen+1u) __nanosleep(32);
            __threadfence();
        }
    }
    __syncthreads();
    gen++;
}

__global__ void __launch_bounds__(256,1) recur_kernel(){
    extern __shared__ unsigned char dyn[];
    float* sC=(float*)(dyn+SC_OFF);
    float* sH=(float*)(dyn+SH_OFF);
    float* sF=(float*)(dyn+SF_OFF);
    const int tid=threadIdx.x, lane=tid&31, w=tid>>5, cta=blockIdx.x;
    const int mi=w&3, kh=w>>2;            // warp = m-tile x K-half
    const uint32_t dynU=(uint32_t)__cvta_generic_to_shared(dyn);

    // preload this CTA's weight slices (frag order, 48KB)
    {
        const uint4* s1=reinterpret_cast<const uint4*>(g_WfaF)+(size_t)cta*1024;
        const uint4* s2=reinterpret_cast<const uint4*>(g_WsaF)+(size_t)cta*1024;
        const uint4* s3=reinterpret_cast<const uint4*>(g_WiaF)+(size_t)cta*1024;
        uint4* d=reinterpret_cast<uint4*>(dyn);
        for(int i=tid;i<1024;i+=256){ d[i]=s1[i]; d[1024+i]=s2[i]; d[2048+i]=s3[i]; }
    }
    for(int i=tid;i<512;i+=256) sH[i]=0.f;
    unsigned gen=0;

    const int arow=mi*16+(lane&7)+((lane>>3)&1)*8;
    const int acol=(lane>>4)*16;
    const int pr=mi*16+(lane>>2), pc=(lane&3)*2;

    for(int t=0;t<T_;t++){
        // ======== phase A: [f|s] = sigmoid(p + h @ [Wfa|Wsa]) ========
        {
            const __half* Ap=g_hall+(size_t)t*(B_*H_);
            float accF[4]={0,0,0,0}, accS[4]={0,0,0,0};
            {
                #pragma unroll
                for(int i=0;i<4;i++){int idx=tid+i*256;int r=idx>>4,ch=idx&15;
                    CPAG(dynU+A_OFF+r*272+ch*16,(const char*)Ap+((size_t)r*H_)*2+ch*16);}
                CPC();
            }
            for(int kt=0;kt<8;kt++){
                int cur=kt&1;
                if(kt<7){
                    #pragma unroll
                    for(int i=0;i<4;i++){int idx=tid+i*256;int r=idx>>4,ch=idx&15;
                        CPAG(dynU+A_OFF+(cur^1)*17408+r*272+ch*16,
                            (const char*)Ap+((size_t)r*H_+(kt+1)*128)*2+ch*16);}
                    CPC(); CPW1();
                } else { CPW0(); }
                __syncthreads();
                #pragma unroll
                for(int kk=0;kk<2;kk++){
                    int ks=kh*4+kk*2;
                    #pragma unroll
                    for(int k2=0;k2<2;k2++){
                        int kss=ks+k2;
                        uint32_t a[4];
                        ldm4(a, dynU+A_OFF+cur*17408+arow*272+kss*32+acol);
                        int kt16=kt*8+kss;
                        uint2 bf=*reinterpret_cast<const uint2*>(dyn+WFA_OFF+((size_t)kt16*32+lane)*8);
                        uint2 bs=*reinterpret_cast<const uint2*>(dyn+WSA_OFF+((size_t)kt16*32+lane)*8);
                        mma16816(accF,a,bf.x,bf.y);
                        mma16816(accS,a,bs.x,bs.y);
                    }
                }
                __syncthreads();
            }
            float* scw=sC+kh*1024;
            scw[pr*16+pc]=accF[0];      scw[pr*16+pc+1]=accF[1];
            scw[(pr+8)*16+pc]=accF[2];  scw[(pr+8)*16+pc+1]=accF[3];
            scw[pr*16+8+pc]=accS[0];    scw[pr*16+8+pc+1]=accS[1];
            scw[(pr+8)*16+8+pc]=accS[2];scw[(pr+8)*16+8+pc+1]=accS[3];
            __syncthreads();
            const float* pA=g_pA+(((size_t)t*128+cta)*64)*16;
            for(int idx=tid;idx<512;idx+=256){
                int b=idx>>3, j=idx&7;
                float f=sigmf(pA[b*16+j]   +sC[b*16+j]   +sC[1024+b*16+j]);
                sF[b*8+j]=f;
                float s=sigmf(pA[b*16+8+j] +sC[b*16+8+j] +sC[1024+b*16+8+j]);
                g_hs16[(size_t)b*H_+cta*8+j]=__float2half_rn(sH[b*8+j]*s);
            }
        }
        grid_barrier(gen);

        // ======== phase B: c = tanh(pi + hs @ Wia); h' = h(1-f)+f*c ========
        {
            const __half* Ap=g_hs16;
            float accC[4]={0,0,0,0};
            {
                #pragma unroll
                for(int i=0;i<4;i++){int idx=tid+i*256;int r=idx>>4,ch=idx&15;
                    CPAG(dynU+A_OFF+r*272+ch*16,(const char*)Ap+((size_t)r*H_)*2+ch*16);}
                CPC();
            }
            for(int kt=0;kt<8;kt++){
                int cur=kt&1;
                if(kt<7){
                    #pragma unroll
                    for(int i=0;i<4;i++){int idx=tid+i*256;int r=idx>>4,ch=idx&15;
                        CPAG(dynU+A_OFF+(cur^1)*17408+r*272+ch*16,
                            (const char*)Ap+((size_t)r*H_+(kt+1)*128)*2+ch*16);}
                    CPC(); CPW1();
                } else { CPW0(); }
                __syncthreads();
                #pragma unroll
                for(int kk=0;kk<4;kk++){
                    int kss=kh*4+kk;
                    uint32_t a[4];
                    ldm4(a, dynU+A_OFF+cur*17408+arow*272+kss*32+acol);
                    int kt16=kt*8+kss;
                    uint2 bi=*reinterpret_cast<const uint2*>(dyn+WIA_OFF+((size_t)kt16*32+lane)*8);
                    mma16816(accC,a,bi.x,bi.y);
                }
                __syncthreads();
            }
            float* scw=sC+kh*1024;
            scw[pr*16+pc]=accC[0];      scw[pr*16+pc+1]=accC[1];
            scw[(pr+8)*16+pc]=accC[2];  scw[(pr+8)*16+pc+1]=accC[3];
            __syncthreads();
            const float* pB=g_pB+(((size_t)t*128+cta)*64)*8;
            __half* hout=g_hall+(size_t)(t+1)*(B_*H_);
            for(int idx=tid;idx<512;idx+=256){
                int b=idx>>3, j=idx&7;
                float cc=tanhf(pB[b*8+j]+sC[b*16+j]+sC[1024+b*16+j]);
                float f=sF[b*8+j], h=sH[b*8+j];
                float hn=h*(1.f-f)+f*cc;
                sH[b*8+j]=hn;
                hout[(size_t)b*H_+cta*8+j]=__float2half_rn(hn);
            }
        }
        grid_barrier(gen);
    }
}

// ---------------- launch ----------------
extern "C" void kernel_launch(void* const* d_in, const int* /*in_sizes*/, int /*n_in*/,
                              void* d_out, int /*out_size*/){
    const float* x    =(const float*)d_in[0];
    const float* fo   =(const float*)d_in[1];
    const float* fi   =(const float*)d_in[2];
    const float* W_fb =(const float*)d_in[3];
    const float* W_fa =(const float*)d_in[4];
    const float* e_f  =(const float*)d_in[5];
    const float* W_ib =(const float*)d_in[6];
    const float* W_ia =(const float*)d_in[7];
    const float* e_i  =(const float*)d_in[8];
    const float* W_sb =(const float*)d_in[9];
    const float* W_sa =(const float*)d_in[10];
    const float* e_s  =(const float*)d_in[11];
    const float* W_ba =(const float*)d_in[12];
    const float* e_o  =(const float*)d_in[13];
    const float* E    =(const float*)d_in[14];
    const int*   midx =(const int*)d_in[15];
    float* out=(float*)d_out;

    cudaFuncSetAttribute(recur_kernel, cudaFuncAttributeMaxDynamicSharedMemorySize, DYN_SZ);

    init_kernel<<<33,256>>>();
    pack_all<<<12288,256>>>(W_fb,W_sb,W_ib,W_fa,W_sa,W_ia,W_ba,E);
    prep_bt<<<(int)(((size_t)R_*DIN+255)/256),256>>>(x,fi);
    prep_dt<<<(int)(((size_t)R_*DD+255)/256),256>>>(fo,midx);

    // MODE0: p = bt@Wb + bias
    { dim3 g(24,64); gemm_fp16<0><<<g,256>>>(e_f,e_s,e_i,nullptr); }
    // recurrence (launch #6 -> ncu capture target)
    recur_kernel<<<GSZ,256,DYN_SZ>>>();
    // MODE1: At = dt@E
    { dim3 g(16,64); gemm_fp16<1><<<g,256>>>(nullptr,nullptr,nullptr,nullptr); }
    // MODE2: out = sigmoid(q*(1+At)+e_o)
    { dim3 g(16,64); gemm_fp16<2><<<g,256>>>(e_o,nullptr,nullptr,out); }
}

// round 6
// speedup vs baseline: 2.9601x; 1.0143x over previous
#include <cuda_runtime.h>
#include <cuda_fp16.h>
#include <cstdint>
#include <cmath>

#define B_   64
#define T_   128
#define DIN  2048
#define H_   1024
#define DD   512
#define R_   (B_*T_)      // 8192 rows, row r = t*64 + b (time-major)
#define GSZ  128          // persistent grid size

// ---------------- device scratch ----------------
__device__ __half  g_bt16[(size_t)R_*DIN];
__device__ __half  g_dt16[(size_t)R_*DD];
__device__ __half  g_At16[(size_t)R_*DIN];
__device__ float   g_pA[(size_t)T_*128*B_*16];   // [t][cta][b][0..7:pf, 8..15:ps]
__device__ float   g_pB[(size_t)T_*128*B_*8];    // [t][cta][b][pi]
__device__ __half  g_hall[(size_t)(T_+1)*B_*H_]; // h per step (slot 0 = zeros)
__device__ __half  g_hs16[(size_t)B_*H_];        // h*s broadcast buffer
// frag-packed weights: layout [nt][kt16][lane][2]u32
__device__ uint2   g_WbF [(size_t)384*128*32];   // [Wfb|Wsb|Wib] K=2048,N=3072
__device__ uint2   g_WfaF[(size_t)128*64*32];    // K=1024,N=1024
__device__ uint2   g_WsaF[(size_t)128*64*32];
__device__ uint2   g_WiaF[(size_t)128*64*32];
__device__ uint2   g_WbaF[(size_t)256*64*32];    // K=1024,N=2048
__device__ uint2   g_EF  [(size_t)256*32*32];    // K=512, N=2048
// flag-tree grid barrier state (padded flags: one per 32B)
__device__ unsigned g_arrive[GSZ*8];
__device__ unsigned g_release;

// ---------------- helpers ----------------
__device__ __forceinline__ float sigmf(float x){ return 1.f/(1.f+expf(-x)); }
__device__ __forceinline__ uint32_t pk2(float a,float b){
    __half2 h=__floats2half2_rn(a,b); return *reinterpret_cast<uint32_t*>(&h);
}
__device__ __forceinline__ void mma16816(float* c,const uint32_t* a,uint32_t b0,uint32_t b1){
    asm volatile("mma.sync.aligned.m16n8k16.row.col.f32.f16.f16.f32 "
        "{%0,%1,%2,%3},{%4,%5,%6,%7},{%8,%9},{%0,%1,%2,%3};"
        : "+f"(c[0]),"+f"(c[1]),"+f"(c[2]),"+f"(c[3])
        : "r"(a[0]),"r"(a[1]),"r"(a[2]),"r"(a[3]),"r"(b0),"r"(b1));
}
__device__ __forceinline__ void ldm4(uint32_t* a,uint32_t addr){
    asm volatile("ldmatrix.sync.aligned.m8n8.x4.shared.b16 {%0,%1,%2,%3},[%4];"
        : "=r"(a[0]),"=r"(a[1]),"=r"(a[2]),"=r"(a[3]) : "r"(addr));
}
// .ca only for addresses never rewritten by other SMs during this launch.
// Cross-CTA recurrent state uses .cg (L2-level).
#define CPA(dst,src)  asm volatile("cp.async.ca.shared.global [%0], [%1], 16;\n"::"r"(dst),"l"(src))
#define CPAG(dst,src) asm volatile("cp.async.cg.shared.global [%0], [%1], 16;\n"::"r"(dst),"l"(src))
#define CPC()  asm volatile("cp.async.commit_group;\n")
template<int N> __device__ __forceinline__ void cpwait(){
    asm volatile("cp.async.wait_group %0;\n"::"n"(N));
}

// ---------------- prep: elementwise fp16 conversions ----------------
__global__ void prep_bt(const float* __restrict__ x,const float* __restrict__ fi){
    size_t i=(size_t)blockIdx.x*256+threadIdx.x;
    if(i>=(size_t)R_*DIN) return;
    size_t r=i/DIN, d=i%DIN;
    int t=(int)(r>>6), b=(int)(r&63);
    size_t base=(size_t)b*T_+t;
    g_bt16[i]=__float2half_rn(x[base*DIN+d]*(1.f-fi[(base*2+1)*DIN+d]));
}
__global__ void prep_dt(const float* __restrict__ fo,const int* __restrict__ midx){
    size_t i=(size_t)blockIdx.x*256+threadIdx.x;
    if(i>=(size_t)R_*DD) return;
    size_t r=i/DD, j=i%DD;
    int t=(int)(r>>6), b=(int)(r&63);
    size_t base=(size_t)b*T_+t;
    g_dt16[i]=__float2half_rn(fo[(base*2+1)*DIN+midx[j]]);
}

// ---------------- pack weights into fragment order ----------------
__device__ __forceinline__ void pack_one(const float* __restrict__ W,int N,int KT16,
                                         size_t i,uint2* __restrict__ dst){
    int lane=(int)(i&31); size_t q=i>>5;
    int kt=(int)(q%KT16); size_t nt=q/KT16;
    int n=(int)nt*8+(lane>>2), k=kt*16+(lane&3)*2;
    uint2 v;
    v.x=pk2(W[(size_t)k*N+n],     W[(size_t)(k+1)*N+n]);
    v.y=pk2(W[(size_t)(k+8)*N+n], W[(size_t)(k+9)*N+n]);
    dst[i]=v;
}
__global__ void pack_all(const float* __restrict__ Wfb,const float* __restrict__ Wsb,
                         const float* __restrict__ Wib,const float* __restrict__ Wfa,
                         const float* __restrict__ Wsa,const float* __restrict__ Wia,
                         const float* __restrict__ Wba,const float* __restrict__ E){
    size_t g=(size_t)blockIdx.x*256+threadIdx.x;
    const size_t n_wb=(size_t)384*128*32;
    const size_t n_sq=(size_t)128*64*32;
    const size_t n_ba=(size_t)256*64*32;
    const size_t n_e =(size_t)256*32*32;
    if(g<n_wb){
        int lane=(int)(g&31); size_t q=g>>5;
        int kt=(int)(q%128); size_t nt=q/128;
        int n=(int)nt*8+(lane>>2), k=kt*16+(lane&3)*2;
        const float* W; int nn;
        if(n<1024){W=Wfb;nn=n;} else if(n<2048){W=Wsb;nn=n-1024;} else {W=Wib;nn=n-2048;}
        uint2 v;
        v.x=pk2(W[(size_t)k*H_+nn],     W[(size_t)(k+1)*H_+nn]);
        v.y=pk2(W[(size_t)(k+8)*H_+nn], W[(size_t)(k+9)*H_+nn]);
        g_WbF[g]=v; return;
    }
    g-=n_wb;
    if(g<n_sq){ pack_one(Wfa,H_,64,g,g_WfaF); return; }
    g-=n_sq;
    if(g<n_sq){ pack_one(Wsa,H_,64,g,g_WsaF); return; }
    g-=n_sq;
    if(g<n_sq){ pack_one(Wia,H_,64,g,g_WiaF); return; }
    g-=n_sq;
    if(g<n_ba){ pack_one(Wba,DIN,64,g,g_WbaF); return; }
    g-=n_ba;                                   // FIXED (was a no-op in R5 -> g_EF never packed -> At=0)
    if(g<n_e ){ pack_one(E,DIN,32,g,g_EF); return; }
}

// ---------------- init ----------------
__global__ void init_kernel(){
    size_t i=(size_t)blockIdx.x*256+threadIdx.x;
    if(i==0) g_release=0u;
    if(i<GSZ) g_arrive[i*8]=0u;
    if(i<8192) reinterpret_cast<uint4*>(g_hall)[i]=make_uint4(0,0,0,0); // slot 0 = zeros
}

// ---------------- big fp16 GEMM, 128x128 CTA tile ----------------
// A and BF are resolved IN-KERNEL (device symbols are not valid host-side).
// MODE 0: p = bt@Wb + bias -> scattered to g_pA/g_pB   (K=2048,N=3072)
// MODE 1: At16 = dt@E                                   (K=512, N=2048)
// MODE 2: out = sigmoid(q*(1+At)+e_o), q = hall@Wba     (K=1024,N=2048)
template<int MODE>
__global__ void __launch_bounds__(256) gemm_fp16(
    const float* __restrict__ e0,const float* __restrict__ e1,
    const float* __restrict__ e2,float* __restrict__ outp)
{
    constexpr int K   =(MODE==0)?2048:((MODE==1)?512:1024);
    constexpr int KT16=K/16;
    constexpr int NKT =K/32;
    const __half* A =(MODE==0)? g_bt16 : ((MODE==1)? g_dt16 : g_hall+(size_t)B_*H_);
    const uint2*  BF=(MODE==0)? g_WbF  : ((MODE==1)? g_EF   : g_WbaF);

    __shared__ __align__(16) unsigned char sA[2][128*80];
    __shared__ __align__(16) unsigned char sB[2][8192];
    const int tid=threadIdx.x, lane=tid&31, w=tid>>5;
    const int m0=blockIdx.y*128, n0=blockIdx.x*128;
    const int wm=(w>>2)*64, wn=(w&3)*32;
    const uint32_t sAu=(uint32_t)__cvta_generic_to_shared(&sA[0][0]);
    float acc[4][4][4]={};

    auto stage=[&](int kt,int bf){
        #pragma unroll
        for(int i=0;i<2;i++){
            int idx=tid+i*256; int r=idx>>2,c=idx&3;
            uint32_t dst=sAu+bf*(128*80)+r*80+c*16;
            const char* src=(const char*)A+((size_t)(m0+r)*K+kt*32)*2+c*16;
            CPA(dst,src);
        }
        #pragma unroll
        for(int i=0;i<2;i++){
            int idx=tid+i*256; int nt=idx>>5,ch=idx&31;
            uint32_t dst=(uint32_t)__cvta_generic_to_shared(&sB[bf][0])+nt*512+ch*16;
            const char* src=(const char*)BF+(((size_t)(n0/8+nt)*KT16+(size_t)kt*2)*256)+ch*16;
            CPA(dst,src);
        }
        CPC();
    };
    stage(0,0);
    for(int kt=0;kt<NKT;kt++){
        int cur=kt&1;
        if(kt+1<NKT){ stage(kt+1,cur^1); cpwait<1>(); } else { cpwait<0>(); }
        __syncthreads();
        #pragma unroll
        for(int kk=0;kk<2;kk++){
            uint32_t a[4][4];
            #pragma unroll
            for(int mi=0;mi<4;mi++){
                int row=wm+mi*16+(lane&7)+((lane>>3)&1)*8;
                ldm4(a[mi], sAu+cur*(128*80)+row*80+kk*32+(lane>>4)*16);
            }
            #pragma unroll
            for(int nj=0;nj<4;nj++){
                const uint2 b=*reinterpret_cast<const uint2*>(&sB[cur][((wn>>3)+nj)*512+kk*256+lane*8]);
                #pragma unroll
                for(int mi=0;mi<4;mi++) mma16816(acc[mi][nj],a[mi],b.x,b.y);
            }
        }
        __syncthreads();
    }
    // epilogue
    #pragma unroll
    for(int mi=0;mi<4;mi++)
    #pragma unroll
    for(int nj=0;nj<4;nj++){
        int c=n0+wn+nj*8+(lane&3)*2;
        #pragma unroll
        for(int p=0;p<2;p++){
            int r=m0+wm+mi*16+(lane>>2)+p*8;
            float d0=acc[mi][nj][p*2], d1=acc[mi][nj][p*2+1];
            int t=r>>6,b=r&63;
            if(MODE==0){
                if(c<1024){
                    float* dst=&g_pA[(((size_t)t*128+(c>>3))*64+b)*16+(c&7)];
                    dst[0]=d0+e0[c]; dst[1]=d1+e0[c+1];
                } else if(c<2048){
                    int n=c-1024;
                    float* dst=&g_pA[(((size_t)t*128+(n>>3))*64+b)*16+8+(n&7)];
                    dst[0]=d0+e1[n]; dst[1]=d1+e1[n+1];
                } else {
                    int n=c-2048;
                    float* dst=&g_pB[(((size_t)t*128+(n>>3))*64+b)*8+(n&7)];
                    dst[0]=d0+e2[n]; dst[1]=d1+e2[n+1];
                }
            } else if(MODE==1){
                *reinterpret_cast<__half2*>(&g_At16[(size_t)r*DIN+c])=__floats2half2_rn(d0,d1);
            } else {
                __half2 ah=*reinterpret_cast<const __half2*>(&g_At16[(size_t)r*DIN+c]);
                float a0=__half2float(__low2half(ah)), a1=__half2float(__high2half(ah));
                float o0=sigmf(d0*(1.f+a0)+e0[c]);
                float o1=sigmf(d1*(1.f+a1)+e0[c+1]);
                *reinterpret_cast<float2*>(&outp[((size_t)b*T_+t)*DIN+c])=make_float2(o0,o1);
            }
        }
    }
}

// ---------------- persistent recurrence ----------------
// dyn smem layout (bytes):
#define WFA_OFF 0          // 16384  [64 kt16][32 lane][u64]
#define WSA_OFF 16384      // 16384
#define WIA_OFF 32768      // 16384
#define A_OFF   49152      // full 64x1024 fp16 tile, row stride 2064B (2064%128==16 -> ldmatrix conflict-free)
#define SPA_OFF 181248     // 4096: staged pA (64x16 f32)
#define SPB_OFF 185344     // 2048: staged pB (64x8 f32)
#define SC_OFF  187392     // 4096: 2 x 64x8 f32 split-K partials (phase B)
#define SH_OFF  191488     // 2048: h columns (64x8 f32)
#define SF_OFF  193536     // 2048: f columns (64x8 f32)
#define DYN_SZ  195584

// flag-tree grid barrier: parallel arrivals, one-warp gather, single release word
__device__ __forceinline__ void grid_barrier(unsigned gen){
    __syncthreads();
    if(blockIdx.x==0){
        if(threadIdx.x<32){
            __threadfence();
            if(threadIdx.x==0) *(volatile unsigned*)&g_arrive[0]=gen;
            bool done=false;
            while(!done){
                bool ok=true;
                #pragma unroll
                for(int k=0;k<4;k++){
                    unsigned v=*(volatile unsigned*)&g_arrive[(threadIdx.x+k*32)*8];
                    if(v<gen) ok=false;
                }
                done=__all_sync(0xFFFFFFFFu, ok);
                if(!done) __nanosleep(20);
            }
            __threadfence();
            if(threadIdx.x==0) *(volatile unsigned*)&g_release=gen;
        }
    } else {
        if(threadIdx.x==0){
            __threadfence();
            *(volatile unsigned*)&g_arrive[blockIdx.x*8]=gen;
            while(*(volatile unsigned*)&g_release < gen) __nanosleep(20);
            __threadfence();
        }
    }
    __syncthreads();
}

__global__ void __launch_bounds__(256,1) recur_kernel(){
    extern __shared__ unsigned char dyn[];
    float* sC =(float*)(dyn+SC_OFF);
    float* sH =(float*)(dyn+SH_OFF);
    float* sF =(float*)(dyn+SF_OFF);
    float* sPA=(float*)(dyn+SPA_OFF);
    float* sPB=(float*)(dyn+SPB_OFF);
    const int tid=threadIdx.x, lane=tid&31, w=tid>>5, cta=blockIdx.x;
    const int mi=w&3, ns=w>>2;            // warp = m-tile x {F,S}/{kh}
    const uint32_t dynU=(uint32_t)__cvta_generic_to_shared(dyn);

    // preload this CTA's weight slices (frag order, 48KB)
    {
        const uint4* s1=reinterpret_cast<const uint4*>(g_WfaF)+(size_t)cta*1024;
        const uint4* s2=reinterpret_cast<const uint4*>(g_WsaF)+(size_t)cta*1024;
        const uint4* s3=reinterpret_cast<const uint4*>(g_WiaF)+(size_t)cta*1024;
        uint4* d=reinterpret_cast<uint4*>(dyn);
        for(int i=tid;i<1024;i+=256){ d[i]=s1[i]; d[1024+i]=s2[i]; d[2048+i]=s3[i]; }
    }
    for(int i=tid;i<512;i+=256) sH[i]=0.f;

    const int arow=mi*16+(lane&7)+((lane>>3)&1)*8;
    const int acol=(lane>>4)*16;
    const int pr=mi*16+(lane>>2), pc=(lane&3)*2;

    for(int t=0;t<T_;t++){
        // ======== phase A: f = sigm(pf + h@Wfa); hs = h * sigm(ps + h@Wsa) ========
        {
            const char* Ap=(const char*)(g_hall+(size_t)t*(B_*H_));
            #pragma unroll
            for(int i=0;i<32;i++){
                int idx=tid+i*256; int r=idx>>7, c=idx&127;
                CPAG(dynU+A_OFF+r*2064+c*16, Ap+(size_t)r*2048+c*16);
            }
            CPC();                                          // group: h tile
            const char* pSrc=(const char*)g_pA+(((size_t)t*128+cta)*1024)*4;
            CPA(dynU+SPA_OFF+tid*16, pSrc+tid*16);
            CPC();                                          // group: pA
            cpwait<1>();                                    // h tile ready
            __syncthreads();
            float acc[4]={0,0,0,0};
            const int WOFF = ns? WSA_OFF : WFA_OFF;
            #pragma unroll 16
            for(int k16=0;k16<64;k16++){
                uint32_t a[4];
                ldm4(a, dynU+A_OFF+arow*2064+k16*32+acol);
                uint2 b=*reinterpret_cast<const uint2*>(dyn+WOFF+((size_t)k16*32+lane)*8);
                mma16816(acc,a,b.x,b.y);
            }
            cpwait<0>();                                    // pA ready
            __syncthreads();
            if(ns==0){
                sF[pr*8+pc]      =sigmf(sPA[pr*16+pc]      +acc[0]);
                sF[pr*8+pc+1]    =sigmf(sPA[pr*16+pc+1]    +acc[1]);
                sF[(pr+8)*8+pc]  =sigmf(sPA[(pr+8)*16+pc]  +acc[2]);
                sF[(pr+8)*8+pc+1]=sigmf(sPA[(pr+8)*16+pc+1]+acc[3]);
            } else {
                float s0=sigmf(sPA[pr*16+8+pc]      +acc[0]);
                float s1=sigmf(sPA[pr*16+8+pc+1]    +acc[1]);
                float s2=sigmf(sPA[(pr+8)*16+8+pc]  +acc[2]);
                float s3=sigmf(sPA[(pr+8)*16+8+pc+1]+acc[3]);
                *reinterpret_cast<__half2*>(&g_hs16[(size_t)pr*H_+cta*8+pc])=
                    __floats2half2_rn(sH[pr*8+pc]*s0, sH[pr*8+pc+1]*s1);
                *reinterpret_cast<__half2*>(&g_hs16[(size_t)(pr+8)*H_+cta*8+pc])=
                    __floats2half2_rn(sH[(pr+8)*8+pc]*s2, sH[(pr+8)*8+pc+1]*s3);
            }
        }
        grid_barrier(2*t+1);

        // ======== phase B: c = tanh(pi + hs@Wia); h' = h(1-f)+f*c ========
        {
            const char* Ap=(const char*)g_hs16;
            #pragma unroll
            for(int i=0;i<32;i++){
                int idx=tid+i*256; int r=idx>>7, c=idx&127;
                CPAG(dynU+A_OFF+r*2064+c*16, Ap+(size_t)r*2048+c*16);
            }
            CPC();                                          // group: hs tile
            const char* pSrc=(const char*)g_pB+(((size_t)t*128+cta)*512)*4;
            if(tid<128) CPA(dynU+SPB_OFF+tid*16, pSrc+tid*16);
            CPC();                                          // group: pB
            cpwait<1>();
            __syncthreads();
            float acc[4]={0,0,0,0};
            #pragma unroll 16
            for(int k=0;k<32;k++){
                int k16=ns*32+k;
                uint32_t a[4];
                ldm4(a, dynU+A_OFF+arow*2064+k16*32+acol);
                uint2 b=*reinterpret_cast<const uint2*>(dyn+WIA_OFF+((size_t)k16*32+lane)*8);
                mma16816(acc,a,b.x,b.y);
            }
            float* scw=sC+ns*512;
            scw[pr*8+pc]      =acc[0]; scw[pr*8+pc+1]    =acc[1];
            scw[(pr+8)*8+pc]  =acc[2]; scw[(pr+8)*8+pc+1]=acc[3];
            cpwait<0>();
            __syncthreads();
            __half* hout=g_hall+(size_t)(t+1)*(B_*H_);
            {
                int b=tid>>2, j=(tid&3)*2;
                float c0=tanhf(sPB[b*8+j]  +sC[b*8+j]  +sC[512+b*8+j]);
                float c1=tanhf(sPB[b*8+j+1]+sC[b*8+j+1]+sC[512+b*8+j+1]);
                float f0=sF[b*8+j], f1=sF[b*8+j+1];
                float h0=sH[b*8+j], h1=sH[b*8+j+1];
                float hn0=h0*(1.f-f0)+f0*c0;
                float hn1=h1*(1.f-f1)+f1*c1;
                sH[b*8+j]=hn0; sH[b*8+j+1]=hn1;
                *reinterpret_cast<__half2*>(&hout[(size_t)b*H_+cta*8+j])=__floats2half2_rn(hn0,hn1);
            }
        }
        grid_barrier(2*t+2);
    }
}

// ---------------- launch ----------------
extern "C" void kernel_launch(void* const* d_in, const int* /*in_sizes*/, int /*n_in*/,
                              void* d_out, int /*out_size*/){
    const float* x    =(const float*)d_in[0];
    const float* fo   =(const float*)d_in[1];
    const float* fi   =(const float*)d_in[2];
    const float* W_fb =(const float*)d_in[3];
    const float* W_fa =(const float*)d_in[4];
    const float* e_f  =(const float*)d_in[5];
    const float* W_ib =(const float*)d_in[6];
    const float* W_ia =(const float*)d_in[7];
    const float* e_i  =(const float*)d_in[8];
    const float* W_sb =(const float*)d_in[9];
    const float* W_sa =(const float*)d_in[10];
    const float* e_s  =(const float*)d_in[11];
    const float* W_ba =(const float*)d_in[12];
    const float* e_o  =(const float*)d_in[13];
    const float* E    =(const float*)d_in[14];
    const int*   midx =(const int*)d_in[15];
    float* out=(float*)d_out;

    cudaFuncSetAttribute(recur_kernel, cudaFuncAttributeMaxDynamicSharedMemorySize, DYN_SZ);

    init_kernel<<<33,256>>>();
    pack_all<<<12288,256>>>(W_fb,W_sb,W_ib,W_fa,W_sa,W_ia,W_ba,E);
    prep_bt<<<(int)(((size_t)R_*DIN+255)/256),256>>>(x,fi);
    prep_dt<<<(int)(((size_t)R_*DD+255)/256),256>>>(fo,midx);

    // MODE0: p = bt@Wb + bias
    { dim3 g(24,64); gemm_fp16<0><<<g,256>>>(e_f,e_s,e_i,nullptr); }
    // recurrence (launch #6 -> ncu capture target)
    recur_kernel<<<GSZ,256,DYN_SZ>>>();
    // MODE1: At = dt@E
    { dim3 g(16,64); gemm_fp16<1><<<g,256>>>(nullptr,nullptr,nullptr,nullptr); }
    // MODE2: out = sigmoid(q*(1+At)+e_o)
    { dim3 g(16,64); gemm_fp16<2><<<g,256>>>(e_o,nullptr,nullptr,out); }
}